// round 15
// baseline (speedup 1.0000x reference)
#include <cuda_runtime.h>
#include <math.h>
#include <stdint.h>

#define T_EN 512
#define T_DE 2048
#define TEMPC 0.0005f
#define NEG_INF_DEV __int_as_float(0xff800000)

__device__ __forceinline__ uint32_t f2tf(float x) {
    uint32_t r;
    asm("cvt.rna.tf32.f32 %0, %1;" : "=r"(r) : "f"(x));
    return r;
}
__device__ __forceinline__ float rtf(float x) { return __uint_as_float(f2tf(x)); }
__device__ __forceinline__ uint32_t smem_u32(const void* p) {
    uint32_t a;
    asm("{ .reg .u64 t; cvta.to.shared.u64 t, %1; cvt.u32.u64 %0, t; }" : "=r"(a) : "l"(p));
    return a;
}
#define LDSM4(r, addr) \
    asm volatile("ldmatrix.sync.aligned.m8n8.x4.shared.b16 {%0,%1,%2,%3}, [%4];" \
                 : "=r"((r)[0]), "=r"((r)[1]), "=r"((r)[2]), "=r"((r)[3]) : "r"(addr))
#define MMA_TF32(d, a, b0, b1) \
    asm volatile("mma.sync.aligned.m16n8k8.row.col.f32.tf32.tf32.f32 " \
                 "{%0,%1,%2,%3}, {%4,%5,%6,%7}, {%8,%9}, {%0,%1,%2,%3};" \
                 : "+f"((d)[0]), "+f"((d)[1]), "+f"((d)[2]), "+f"((d)[3]) \
                 : "r"((a)[0]), "r"((a)[1]), "r"((a)[2]), "r"((a)[3]), "r"(b0), "r"(b1))

// ------------------------- scratch (device globals) -------------------------
__device__ float g_xr[32L * 512 * 512];
__device__ float g_yr[32L * 2048 * 80];
__device__ float g_Wt1[1024L * 1536];
__device__ float g_Wq1[160 * 240];
__device__ float g_Wk2[128 * 1024];
__device__ float g_Wq2[80 * 160];
__device__ float g_Wq3[128 * 80];
__device__ float g_h1[16384L * 1024];
__device__ float g_kk[16384L * 128];
__device__ float g_k2[16384];
__device__ float g_hq1[65536L * 160];
__device__ float g_hq2[65536L * 80];
__device__ float g_qq[65536L * 128];
__device__ float g_q2[65536];
__device__ float g_logits[33554432L];
__device__ unsigned g_dirT[32L * 512 * 64];
__device__ int g_idx[32 * 2048];

// ------------------------- merged weight prep -------------------------
#define WT1_N (1024 * 512 * 3)
#define WQ1_N (160 * 80 * 3)
__global__ void prep_all(const float* __restrict__ kw1, const float* __restrict__ qw1,
                         const float* __restrict__ kw2, const float* __restrict__ qw2,
                         const float* __restrict__ qw3,
                         float* __restrict__ Wt1, float* __restrict__ Wq1,
                         float* __restrict__ Wk2, float* __restrict__ Wq2,
                         float* __restrict__ Wq3) {
    int i = blockIdx.x * 256 + threadIdx.x;
    if (i < WT1_N) {
        int n = i / 1536, rem = i - n * 1536;
        int ci = rem / 3, dt = rem - ci * 3;
        Wt1[(long)n * 1536 + dt * 512 + ci] = rtf(kw1[i]);
        return;
    }
    i -= WT1_N;
    if (i < WQ1_N) {
        int n = i / 240, rem = i - n * 240;
        int ci = rem / 3, dt = rem - ci * 3;
        Wq1[n * 240 + dt * 80 + ci] = rtf(qw1[i]);
        return;
    }
    i -= WQ1_N;
    if (i < 131072) { Wk2[i] = rtf(kw2[i]); return; }
    i -= 131072;
    if (i < 12800) { Wq2[i] = rtf(qw2[i]); return; }
    i -= 12800;
    if (i < 10240) { Wq3[i] = rtf(qw3[i]); return; }
}
#define PREP_TOTAL (WT1_N + WQ1_N + 131072 + 12800 + 10240)

#define XN4 2097152
#define YN4 1310720
__global__ void roundcopy_xy(const float* __restrict__ x, const float* __restrict__ y,
                             float* __restrict__ xr, float* __restrict__ yr) {
    int i = blockIdx.x * 256 + threadIdx.x;
    const float4* in;
    float4* out;
    if (i < XN4) { in = (const float4*)x + i; out = (float4*)xr + i; }
    else if (i < XN4 + YN4) { in = (const float4*)y + (i - XN4); out = (float4*)yr + (i - XN4); }
    else return;
    float4 v = *in;
    v.x = rtf(v.x); v.y = rtf(v.y); v.z = rtf(v.z); v.w = rtf(v.w);
    *out = v;
}

// ------------------------- tf32 cp.async + ldmatrix GEMM (v5 + dead-N guard) -------------------------
template <int IM2COL, int EPI, int CIN, int TLEN>
__global__ __launch_bounds__(256, 2) void tgemm(
    const float* __restrict__ A, const float* __restrict__ B,
    const float* __restrict__ bias, float* __restrict__ C,
    int N, int Kreal, int ldA, int ldB, int ldC,
    long sAb, long sBb, long sCb,
    const float* __restrict__ rown, const float* __restrict__ coln,
    int rstride, int cstride)
{
    extern __shared__ float smf[];
    const uint32_t smb = smem_u32(smf);
    const int tid = threadIdx.x, lane = tid & 31, wid = tid >> 5;
    const int bn = blockIdx.x * 128, bm = blockIdx.y * 128, bz = blockIdx.z;
    A += sAb * bz; B += sBb * bz;
    const int wm = wid & 3, wn = wid >> 2;

    float acc[2][8][4];
#pragma unroll
    for (int i = 0; i < 2; i++)
#pragma unroll
        for (int j = 0; j < 8; j++)
#pragma unroll
            for (int q = 0; q < 4; q++) acc[i][j][q] = 0.f;

    const int nc = (Kreal + 31) >> 5;

    auto prefetch = [&](int c, int s) {
        const int kb = c << 5;
        const uint32_t sbase = smb + (uint32_t)s * 32768u;
#pragma unroll
        for (int r = 0; r < 4; r++) {
            int f = tid + r * 256;
            int row = f >> 3, kq = f & 7;
            int gk = kb + kq * 4;
            uint32_t dsw = (uint32_t)(row * 128 + ((kq ^ (row & 7)) << 4));
            {
                const float* src = A;
                int sz = 0;
                if (gk < Kreal) {
                    if (IM2COL) {
                        int gm = bm + row;
                        int bb = gm / TLEN;
                        int t = gm - bb * TLEN;
                        int dt = gk / CIN;
                        int ci = gk - dt * CIN;
                        int tt = t + dt - 1;
                        if (tt >= 0 && tt < TLEN) {
                            src = A + ((long)(bb * TLEN + tt)) * CIN + ci;
                            sz = 16;
                        }
                    } else {
                        src = A + (long)(bm + row) * ldA + gk;
                        sz = 16;
                    }
                }
                asm volatile("cp.async.cg.shared.global [%0], [%1], 16, %2;"
                             :: "r"(sbase + dsw), "l"(src), "r"(sz) : "memory");
            }
            {
                const float* src = B;
                int sz = 0;
                if ((bn + row) < N && gk < Kreal) {
                    src = B + (long)(bn + row) * ldB + gk;
                    sz = 16;
                }
                asm volatile("cp.async.cg.shared.global [%0], [%1], 16, %2;"
                             :: "r"(sbase + 16384u + dsw), "l"(src), "r"(sz) : "memory");
            }
        }
        asm volatile("cp.async.commit_group;" ::: "memory");
    };

    prefetch(0, 0);
    prefetch(1, 1);

    uint32_t aAddr[2];
    {
        int l16 = lane >> 4;
#pragma unroll
        for (int mi = 0; mi < 2; mi++) {
            int row = wm * 32 + mi * 16 + (lane & 15);
            aAddr[mi] = (uint32_t)(row * 128 + ((l16 ^ (row & 7)) << 4));
        }
    }
    uint32_t bAddr[4];
    {
        int brlo = (lane & 7) + ((lane >> 4) << 3);
        int bk = (lane >> 3) & 1;
#pragma unroll
        for (int nb = 0; nb < 4; nb++) {
            int row = wn * 64 + nb * 16 + brlo;
            bAddr[nb] = (uint32_t)(16384 + row * 128 + ((bk ^ (row & 7)) << 4));
        }
    }
    // warp-uniform validity of each 16-col n-fragment group (skip dead MMAs)
    bool nbOK[4];
#pragma unroll
    for (int nb = 0; nb < 4; nb++) nbOK[nb] = (bn + wn * 64 + nb * 16) < N;

    int st_cur = 0, st_pf = 2;
    for (int c = 0; c < nc; c++) {
        asm volatile("cp.async.wait_group 1;" ::: "memory");
        __syncthreads();
        if (c + 2 < nc) prefetch(c + 2, st_pf);
        else asm volatile("cp.async.commit_group;" ::: "memory");
        st_pf = (st_pf == 2) ? 0 : st_pf + 1;

        const uint32_t sbase = smb + (uint32_t)st_cur * 32768u;
        st_cur = (st_cur == 2) ? 0 : st_cur + 1;
#pragma unroll
        for (int ks = 0; ks < 4; ks++) {
            const uint32_t kx = (uint32_t)(ks << 5);
            uint32_t a0[4], a1[4];
            LDSM4(a0, sbase + (aAddr[0] ^ kx));
            LDSM4(a1, sbase + (aAddr[1] ^ kx));
#pragma unroll
            for (int nb = 0; nb < 4; nb++) {
                if (nbOK[nb]) {
                    uint32_t bv[4];
                    LDSM4(bv, sbase + (bAddr[nb] ^ kx));
                    MMA_TF32(acc[0][nb * 2], a0, bv[0], bv[1]);
                    MMA_TF32(acc[1][nb * 2], a1, bv[0], bv[1]);
                    MMA_TF32(acc[0][nb * 2 + 1], a0, bv[2], bv[3]);
                    MMA_TF32(acc[1][nb * 2 + 1], a1, bv[2], bv[3]);
                }
            }
        }
    }

    // ---- epilogue ----
    const int qrow = lane >> 2, klo = lane & 3;
    float* sqsh = smf;
    if (EPI == 3) {
        __syncthreads();
        if (tid < 128) sqsh[tid] = 0.f;
        __syncthreads();
    }
    C += sCb * bz;
#pragma unroll
    for (int mi = 0; mi < 2; mi++) {
        int r0 = bm + wm * 32 + mi * 16 + qrow;
        float ra0 = 0.f, ra1 = 0.f;
        if (EPI == 2) {
            ra0 = rown[(long)rstride * bz + r0];
            ra1 = rown[(long)rstride * bz + r0 + 8];
        }
        float s_lo = 0.f, s_hi = 0.f;
#pragma unroll
        for (int ni = 0; ni < 8; ni++) {
            int colb = bn + wn * 64 + ni * 8;
            if (colb < N) {
                int col = colb + klo * 2;
                float2 v0, v1;
                if (EPI == 2) {
                    float cn0 = coln[(long)cstride * bz + col];
                    float cn1 = coln[(long)cstride * bz + col + 1];
                    v0.x = -TEMPC * (ra0 + cn0 - 2.f * acc[mi][ni][0]);
                    v0.y = -TEMPC * (ra0 + cn1 - 2.f * acc[mi][ni][1]);
                    v1.x = -TEMPC * (ra1 + cn0 - 2.f * acc[mi][ni][2]);
                    v1.y = -TEMPC * (ra1 + cn1 - 2.f * acc[mi][ni][3]);
                } else {
                    float bb0 = bias[col], bb1 = bias[col + 1];
                    v0.x = acc[mi][ni][0] + bb0; v0.y = acc[mi][ni][1] + bb1;
                    v1.x = acc[mi][ni][2] + bb0; v1.y = acc[mi][ni][3] + bb1;
                    if (EPI == 1) {
                        v0.x = fmaxf(v0.x, 0.f); v0.y = fmaxf(v0.y, 0.f);
                        v1.x = fmaxf(v1.x, 0.f); v1.y = fmaxf(v1.y, 0.f);
                    }
                    v0.x = rtf(v0.x); v0.y = rtf(v0.y);
                    v1.x = rtf(v1.x); v1.y = rtf(v1.y);
                    if (EPI == 3) {
                        s_lo += v0.x * v0.x + v0.y * v0.y;
                        s_hi += v1.x * v1.x + v1.y * v1.y;
                    }
                }
                *(float2*)(C + (long)r0 * ldC + col) = v0;
                *(float2*)(C + (long)(r0 + 8) * ldC + col) = v1;
            }
        }
        if (EPI == 3) {
            s_lo += __shfl_xor_sync(0xffffffffu, s_lo, 1);
            s_lo += __shfl_xor_sync(0xffffffffu, s_lo, 2);
            s_hi += __shfl_xor_sync(0xffffffffu, s_hi, 1);
            s_hi += __shfl_xor_sync(0xffffffffu, s_hi, 2);
            if (klo == 0) {
                int lr = wm * 32 + mi * 16 + qrow;
                atomicAdd(&sqsh[lr], s_lo);
                atomicAdd(&sqsh[lr + 8], s_hi);
            }
        }
    }
    if (EPI == 3) {
        __syncthreads();
        if (tid < 128) ((float*)coln)[bm + tid] = sqsh[tid];
    }
}

// ------------------------- fused prior + log_softmax + softmax -------------------------
// Blocks remapped in REVERSE order so the first logits reads hit the L2 tail
// left by the dist GEMM (logits ~128MB vs 126MB L2). Pure index remap.
__global__ __launch_bounds__(512) void softprior(
    const float* __restrict__ logits, const float* __restrict__ prior,
    float* __restrict__ out_logp, float* __restrict__ out_attn)
{
    __shared__ float sp[512][17];
    const int b = 31 - blockIdx.y;
    const int t0 = (127 - blockIdx.x) * 16;
    const int tid = threadIdx.x, lane = tid & 31, wid = tid >> 5;
#pragma unroll
    for (int i = 0; i < 4; i++) {
        int f = tid + i * 512;
        int s = f >> 2;
        int tt4 = (f & 3) * 4;
        float4 v = *(const float4*)(prior + ((long)(b * 512 + s)) * 2048 + t0 + tt4);
        sp[s][tt4 + 0] = v.x; sp[s][tt4 + 1] = v.y;
        sp[s][tt4 + 2] = v.z; sp[s][tt4 + 3] = v.w;
    }
    __syncthreads();

    const long row = (long)b * 2048 + t0 + wid;
    const float* lrow = logits + row * 512;
    float v[16], e[16], p[16];
#pragma unroll
    for (int i = 0; i < 16; i++) v[i] = lrow[lane + 32 * i];
    float m = v[0];
#pragma unroll
    for (int i = 1; i < 16; i++) m = fmaxf(m, v[i]);
#pragma unroll
    for (int o = 16; o; o >>= 1) m = fmaxf(m, __shfl_xor_sync(0xffffffffu, m, o));
    float s1 = 0.f;
#pragma unroll
    for (int i = 0; i < 16; i++) { e[i] = __expf(v[i] - m); s1 += e[i]; }
#pragma unroll
    for (int o = 16; o; o >>= 1) s1 += __shfl_xor_sync(0xffffffffu, s1, o);
    float lse = m + __logf(s1);
    float den = 0.f;
#pragma unroll
    for (int i = 0; i < 16; i++) {
        p[i] = sp[lane + 32 * i][wid] + 1e-8f;
        den += e[i] * p[i];
    }
#pragma unroll
    for (int o = 16; o; o >>= 1) den += __shfl_xor_sync(0xffffffffu, den, o);
    float inv = 1.f / den;
    float* lpo = out_logp + row * 512;
    float* ao = out_attn + row * 512;
#pragma unroll
    for (int i = 0; i < 16; i++) {
        lpo[lane + 32 * i] = v[i] - lse + __logf(p[i]);
        ao[lane + 32 * i] = e[i] * p[i] * inv;
    }
}

// ------------------------- MAS forward DP v2: 2-row/2-step trapezoid (round-11 proven) -------------------------
__global__ __launch_bounds__(256) void mas_fwd(const float* __restrict__ attn,
                                               unsigned* __restrict__ dirT)
{
    const int b = blockIdx.x;
    const int t = threadIdx.x;
    const int i0 = 2 * t;
    __shared__ float colb[16][512];
    __shared__ float nbr[2][256][2];
    const float* abase = attn + (long)b * 2048 * 512;
    const uint32_t cb = smem_u32(&colb[0][0]);

    nbr[0][t][0] = 0.f; nbr[0][t][1] = 0.f;
    for (int c = 0; c < 14; c += 2) {
#pragma unroll
        for (int cc = 0; cc < 2; cc++) {
            int col = c + cc;
            uint32_t dst = cb + (uint32_t)(((col & 15) * 512 + i0) * 4);
            asm volatile("cp.async.ca.shared.global [%0], [%1], 8;"
                         :: "r"(dst), "l"(abase + (long)col * 512 + i0) : "memory");
        }
        asm volatile("cp.async.commit_group;" ::: "memory");
    }
    float v0 = 0.f, v1 = 0.f;
    unsigned dw0 = 0, dw1 = 0;
    int p = 0;
    const int loA = (t == 0) ? 0 : (i0 - 1);

    for (int j0 = 0; j0 < 2048; j0 += 2) {
        asm volatile("cp.async.wait_group 6;" ::: "memory");
        __syncthreads();
        const int s0 = j0 & 15;
        float a0m1 = colb[s0][loA];
        float2 a0 = *(float2*)&colb[s0][i0];
        float2 a1 = *(float2*)&colb[s0 | 1][i0];
        float w0, w1;
        if (t == 0) { w0 = NEG_INF_DEV; w1 = NEG_INF_DEV; }
        else { w0 = nbr[p][t - 1][0]; w1 = nbr[p][t - 1][1]; }
        float w2 = v0, w3 = v1;
        {
            bool d3 = (w3 >= w2);
            bool d2 = (w2 >= w1);
            float c3 = fmaxf(w3, w2) + a0.y;
            float c2 = fmaxf(w2, w1) + a0.x;
            float c1 = fmaxf(w1, w0) + a0m1;
            w3 = (i0 + 1 <= j0) ? c3 : NEG_INF_DEV;
            w2 = (i0 <= j0) ? c2 : NEG_INF_DEV;
            w1 = (i0 - 1 <= j0) ? c1 : NEG_INF_DEV;
            dw1 |= ((unsigned)d3) << (j0 & 31);
            dw0 |= ((unsigned)d2) << (j0 & 31);
        }
        {
            const int j = j0 + 1;
            bool d3 = (w3 >= w2);
            bool d2 = (w2 >= w1);
            float c3 = fmaxf(w3, w2) + a1.y;
            float c2 = fmaxf(w2, w1) + a1.x;
            w3 = (i0 + 1 <= j) ? c3 : NEG_INF_DEV;
            w2 = (i0 <= j) ? c2 : NEG_INF_DEV;
            dw1 |= ((unsigned)d3) << (j & 31);
            dw0 |= ((unsigned)d2) << (j & 31);
        }
        v0 = w2; v1 = w3;
        nbr[p ^ 1][t][0] = v0; nbr[p ^ 1][t][1] = v1;
        p ^= 1;
        if (((j0 + 1) & 31) == 31) {
            int jw = j0 >> 5;
            dirT[((long)b * 512 + i0) * 64 + jw] = dw0;
            dirT[((long)b * 512 + i0 + 1) * 64 + jw] = dw1;
            dw0 = 0; dw1 = 0;
        }
        if (j0 + 14 < 2048) {
#pragma unroll
            for (int cc = 0; cc < 2; cc++) {
                int col = j0 + 14 + cc;
                uint32_t dst = cb + (uint32_t)(((col & 15) * 512 + i0) * 4);
                asm volatile("cp.async.ca.shared.global [%0], [%1], 8;"
                             :: "r"(dst), "l"(abase + (long)col * 512 + i0) : "memory");
            }
        }
        asm volatile("cp.async.commit_group;" ::: "memory");
    }
}

// ------------------------- MAS backtrack (word-scan runs) -------------------------
__global__ __launch_bounds__(512) void mas_bwd(const unsigned* __restrict__ dirT,
                                               int* __restrict__ idxg,
                                               float* __restrict__ durf)
{
    extern __shared__ unsigned sd[];
    __shared__ unsigned short sjlo[512];
    __shared__ unsigned short sidx[2048];
    int b = blockIdx.x, tid = threadIdx.x;
    for (int f = tid; f < 32768; f += 512) sd[f] = dirT[(long)b * 32768 + f];
    __syncthreads();
    if (tid == 0) {
        int idx = 511, j = 2047;
        while (idx > 0 && j >= 0) {
            unsigned w = sd[idx * 64 + (j >> 5)];
            int pj = j & 31;
            unsigned z = (~w) & ((2u << pj) - 1u);
            if (z == 0) {
                j -= pj + 1;
            } else {
                int hb = 31 - __clz(z);
                int jlo = (j & ~31) + hb;
                sjlo[idx] = (unsigned short)jlo;
                idx--;
                j = jlo - 1;
            }
        }
        sjlo[0] = 0;
    }
    __syncthreads();
    {
        int jlo = sjlo[tid];
        int jhi = (tid == 511) ? 2047 : ((int)sjlo[tid + 1] - 1);
        durf[b * 512 + tid] = (float)(jhi - jlo + 1);
        for (int j = jlo; j <= jhi; j++) sidx[j] = (unsigned short)tid;
    }
    __syncthreads();
    for (int f = tid; f < 2048; f += 512) idxg[b * 2048 + f] = (int)sidx[f];
}

__global__ __launch_bounds__(128) void mas_fill(const int* __restrict__ idxg,
                                                float* __restrict__ masout)
{
    long row = blockIdx.x;
    int id = idxg[row];
    int tid = threadIdx.x;
    float4 v = make_float4(0.f, 0.f, 0.f, 0.f);
    if ((id >> 2) == tid) ((float*)&v)[id & 3] = 1.f;
    ((float4*)(masout + row * 512))[tid] = v;
}

// ------------------------- launcher -------------------------
#define GSMEM 98304

extern "C" void kernel_launch(void* const* d_in, const int* in_sizes, int n_in,
                              void* d_out, int out_size) {
    const float* x   = (const float*)d_in[0];   // [32,512,512]
    const float* y   = (const float*)d_in[1];   // [32,2048,80]
    const float* pr  = (const float*)d_in[4];   // [32,512,2048]
    const float* kw1 = (const float*)d_in[5];
    const float* kb1 = (const float*)d_in[6];
    const float* kw2 = (const float*)d_in[7];
    const float* kb2 = (const float*)d_in[8];
    const float* qw1 = (const float*)d_in[9];
    const float* qb1 = (const float*)d_in[10];
    const float* qw2 = (const float*)d_in[11];
    const float* qb2 = (const float*)d_in[12];
    const float* qw3 = (const float*)d_in[13];
    const float* qb3 = (const float*)d_in[14];

    float* out = (float*)d_out;
    float* out_logp = out;
    float* out_attn = out + 33554432L;
    float* out_mas  = out + 67108864L;
    float* out_dur  = out + 100663296L;

    float *xr, *yr, *Wt1, *Wq1, *Wk2, *Wq2, *Wq3;
    float *h1, *kk, *k2, *hq1, *hq2, *qq, *q2, *logits;
    unsigned* dirT; int* idxg;
    cudaGetSymbolAddress((void**)&xr, g_xr);
    cudaGetSymbolAddress((void**)&yr, g_yr);
    cudaGetSymbolAddress((void**)&Wt1, g_Wt1);
    cudaGetSymbolAddress((void**)&Wq1, g_Wq1);
    cudaGetSymbolAddress((void**)&Wk2, g_Wk2);
    cudaGetSymbolAddress((void**)&Wq2, g_Wq2);
    cudaGetSymbolAddress((void**)&Wq3, g_Wq3);
    cudaGetSymbolAddress((void**)&h1, g_h1);
    cudaGetSymbolAddress((void**)&kk, g_kk);
    cudaGetSymbolAddress((void**)&k2, g_k2);
    cudaGetSymbolAddress((void**)&hq1, g_hq1);
    cudaGetSymbolAddress((void**)&hq2, g_hq2);
    cudaGetSymbolAddress((void**)&qq, g_qq);
    cudaGetSymbolAddress((void**)&q2, g_q2);
    cudaGetSymbolAddress((void**)&logits, g_logits);
    cudaGetSymbolAddress((void**)&dirT, g_dirT);
    cudaGetSymbolAddress((void**)&idxg, g_idx);

    cudaFuncSetAttribute(tgemm<1, 1, 512, 512>, cudaFuncAttributeMaxDynamicSharedMemorySize, GSMEM);
    cudaFuncSetAttribute(tgemm<1, 1, 80, 2048>, cudaFuncAttributeMaxDynamicSharedMemorySize, GSMEM);
    cudaFuncSetAttribute(tgemm<0, 1, 0, 0>, cudaFuncAttributeMaxDynamicSharedMemorySize, GSMEM);
    cudaFuncSetAttribute(tgemm<0, 2, 0, 0>, cudaFuncAttributeMaxDynamicSharedMemorySize, GSMEM);
    cudaFuncSetAttribute(tgemm<0, 3, 0, 0>, cudaFuncAttributeMaxDynamicSharedMemorySize, GSMEM);
    cudaFuncSetAttribute(mas_bwd, cudaFuncAttributeMaxDynamicSharedMemorySize, 131072);

    // 1-2: prep (tf32-round everything entering MMAs)
    roundcopy_xy<<<(XN4 + YN4 + 255) / 256, 256>>>(x, y, xr, yr);
    prep_all<<<(PREP_TOTAL + 255) / 256, 256>>>(kw1, qw1, kw2, qw2, qw3,
                                                Wt1, Wq1, Wk2, Wq2, Wq3);

    // 3: k conv3 (im2col) M=16384 N=1024 K=1536, relu'd
    tgemm<1, 1, 512, 512><<<dim3(8, 128, 1), 256, GSMEM>>>(
        xr, Wt1, kb1, h1, 1024, 1536, 0, 1536, 1024,
        0, 0, 0, nullptr, nullptr, 0, 0);
    // 4: k 1x1 M=16384 N=128 K=1024 -> kk + k2 (rowsq fused)
    tgemm<0, 3, 0, 0><<<dim3(1, 128, 1), 256, GSMEM>>>(
        h1, Wk2, kb2, kk, 128, 1024, 1024, 1024, 128,
        0, 0, 0, nullptr, k2, 0, 0);

    // 5: q conv3 M=65536 N=160 K=240, relu'd
    tgemm<1, 1, 80, 2048><<<dim3(2, 512, 1), 256, GSMEM>>>(
        yr, Wq1, qb1, hq1, 160, 240, 0, 240, 160,
        0, 0, 0, nullptr, nullptr, 0, 0);
    // 6: q 1x1 N=80 K=160, relu'd
    tgemm<0, 1, 0, 0><<<dim3(1, 512, 1), 256, GSMEM>>>(
        hq1, Wq2, qb2, hq2, 80, 160, 160, 160, 80,
        0, 0, 0, nullptr, nullptr, 0, 0);
    // 7: q 1x1 N=128 K=80 -> qq + q2 (rowsq fused)
    tgemm<0, 3, 0, 0><<<dim3(1, 512, 1), 256, GSMEM>>>(
        hq2, Wq3, qb3, qq, 128, 80, 80, 80, 128,
        0, 0, 0, nullptr, q2, 0, 0);

    // 8: dist GEMM (batched): logits[b][t][s] = -TEMP*(q2+k2-2qk)
    tgemm<0, 2, 0, 0><<<dim3(4, 16, 32), 256, GSMEM>>>(
        qq, kk, nullptr, logits, 512, 128, 128, 128, 512,
        2048L * 128, 512L * 128, 2048L * 512, q2, k2, 2048, 512);

    // 9: fused prior + log_softmax + softmax (reverse-order blocks for L2 reuse)
    softprior<<<dim3(128, 32), 512>>>(logits, pr, out_logp, out_attn);

    // 10-12: MAS forward DP + backtrack + fill
    mas_fwd<<<32, 256>>>(out_attn, dirT);
    mas_bwd<<<32, 512, 131072>>>(dirT, idxg, out_dur);
    mas_fill<<<65536, 128>>>(idxg, out_mas);
}

// round 16
// speedup vs baseline: 1.0721x; 1.0721x over previous
#include <cuda_runtime.h>
#include <math.h>
#include <stdint.h>

#define T_EN 512
#define T_DE 2048
#define TEMPC 0.0005f
#define NEG_INF_DEV __int_as_float(0xff800000)

__device__ __forceinline__ uint32_t f2tf(float x) {
    uint32_t r;
    asm("cvt.rna.tf32.f32 %0, %1;" : "=r"(r) : "f"(x));
    return r;
}
__device__ __forceinline__ float rtf(float x) { return __uint_as_float(f2tf(x)); }
__device__ __forceinline__ uint32_t smem_u32(const void* p) {
    uint32_t a;
    asm("{ .reg .u64 t; cvta.to.shared.u64 t, %1; cvt.u32.u64 %0, t; }" : "=r"(a) : "l"(p));
    return a;
}
#define LDSM4(r, addr) \
    asm volatile("ldmatrix.sync.aligned.m8n8.x4.shared.b16 {%0,%1,%2,%3}, [%4];" \
                 : "=r"((r)[0]), "=r"((r)[1]), "=r"((r)[2]), "=r"((r)[3]) : "r"(addr))
#define MMA_TF32(d, a, b0, b1) \
    asm volatile("mma.sync.aligned.m16n8k8.row.col.f32.tf32.tf32.f32 " \
                 "{%0,%1,%2,%3}, {%4,%5,%6,%7}, {%8,%9}, {%0,%1,%2,%3};" \
                 : "+f"((d)[0]), "+f"((d)[1]), "+f"((d)[2]), "+f"((d)[3]) \
                 : "r"((a)[0]), "r"((a)[1]), "r"((a)[2]), "r"((a)[3]), "r"(b0), "r"(b1))

// ------------------------- scratch (device globals) -------------------------
__device__ float g_xr[32L * 512 * 512];
__device__ float g_yr[32L * 2048 * 80];
__device__ float g_Wt1[1024L * 1536];
__device__ float g_Wq1[160 * 240];
__device__ float g_Wk2[128 * 1024];
__device__ float g_Wq2[80 * 160];
__device__ float g_Wq3[128 * 80];
__device__ float g_h1[16384L * 1024];
__device__ float g_kk[16384L * 128];
__device__ float g_k2[16384];
__device__ float g_hq1[65536L * 160];
__device__ float g_hq2[65536L * 80];
__device__ float g_qq[65536L * 128];
__device__ float g_q2[65536];
__device__ float g_logits[33554432L];
__device__ unsigned g_dirT[32L * 512 * 64];
__device__ int g_idx[32 * 2048];

// ------------------------- merged prep: roundcopy(x,y) + weight prep -------------------------
#define WT1_N (1024 * 512 * 3)
#define WQ1_N (160 * 80 * 3)
#define PREP_TOTAL (WT1_N + WQ1_N + 131072 + 12800 + 10240)
#define XN4 2097152
#define YN4 1310720
#define RC_BLOCKS ((XN4 + YN4 + 255) / 256)
#define PREP_BLOCKS ((PREP_TOTAL + 255) / 256)

__global__ void prep_merged(const float* __restrict__ x, const float* __restrict__ y,
                            float* __restrict__ xr, float* __restrict__ yr,
                            const float* __restrict__ kw1, const float* __restrict__ qw1,
                            const float* __restrict__ kw2, const float* __restrict__ qw2,
                            const float* __restrict__ qw3,
                            float* __restrict__ Wt1, float* __restrict__ Wq1,
                            float* __restrict__ Wk2, float* __restrict__ Wq2,
                            float* __restrict__ Wq3) {
    if (blockIdx.x < RC_BLOCKS) {
        int i = blockIdx.x * 256 + threadIdx.x;
        const float4* in;
        float4* out;
        if (i < XN4) { in = (const float4*)x + i; out = (float4*)xr + i; }
        else if (i < XN4 + YN4) { in = (const float4*)y + (i - XN4); out = (float4*)yr + (i - XN4); }
        else return;
        float4 v = *in;
        v.x = rtf(v.x); v.y = rtf(v.y); v.z = rtf(v.z); v.w = rtf(v.w);
        *out = v;
        return;
    }
    int i = (blockIdx.x - RC_BLOCKS) * 256 + threadIdx.x;
    if (i < WT1_N) {
        int n = i / 1536, rem = i - n * 1536;
        int ci = rem / 3, dt = rem - ci * 3;
        Wt1[(long)n * 1536 + dt * 512 + ci] = rtf(kw1[i]);
        return;
    }
    i -= WT1_N;
    if (i < WQ1_N) {
        int n = i / 240, rem = i - n * 240;
        int ci = rem / 3, dt = rem - ci * 3;
        Wq1[n * 240 + dt * 80 + ci] = rtf(qw1[i]);
        return;
    }
    i -= WQ1_N;
    if (i < 131072) { Wk2[i] = rtf(kw2[i]); return; }
    i -= 131072;
    if (i < 12800) { Wq2[i] = rtf(qw2[i]); return; }
    i -= 12800;
    if (i < 10240) { Wq3[i] = rtf(qw3[i]); return; }
}

// ------------------------- tf32 cp.async + ldmatrix GEMM (round-11 exact) -------------------------
template <int IM2COL, int EPI, int CIN, int TLEN>
__global__ __launch_bounds__(256, 2) void tgemm(
    const float* __restrict__ A, const float* __restrict__ B,
    const float* __restrict__ bias, float* __restrict__ C,
    int N, int Kreal, int ldA, int ldB, int ldC,
    long sAb, long sBb, long sCb,
    const float* __restrict__ rown, const float* __restrict__ coln,
    int rstride, int cstride)
{
    extern __shared__ float smf[];
    const uint32_t smb = smem_u32(smf);
    const int tid = threadIdx.x, lane = tid & 31, wid = tid >> 5;
    const int bn = blockIdx.x * 128, bm = blockIdx.y * 128, bz = blockIdx.z;
    A += sAb * bz; B += sBb * bz;
    const int wm = wid & 3, wn = wid >> 2;

    float acc[2][8][4];
#pragma unroll
    for (int i = 0; i < 2; i++)
#pragma unroll
        for (int j = 0; j < 8; j++)
#pragma unroll
            for (int q = 0; q < 4; q++) acc[i][j][q] = 0.f;

    const int nc = (Kreal + 31) >> 5;

    auto prefetch = [&](int c, int s) {
        const int kb = c << 5;
        const uint32_t sbase = smb + (uint32_t)s * 32768u;
#pragma unroll
        for (int r = 0; r < 4; r++) {
            int f = tid + r * 256;
            int row = f >> 3, kq = f & 7;
            int gk = kb + kq * 4;
            uint32_t dsw = (uint32_t)(row * 128 + ((kq ^ (row & 7)) << 4));
            {
                const float* src = A;
                int sz = 0;
                if (gk < Kreal) {
                    if (IM2COL) {
                        int gm = bm + row;
                        int bb = gm / TLEN;
                        int t = gm - bb * TLEN;
                        int dt = gk / CIN;
                        int ci = gk - dt * CIN;
                        int tt = t + dt - 1;
                        if (tt >= 0 && tt < TLEN) {
                            src = A + ((long)(bb * TLEN + tt)) * CIN + ci;
                            sz = 16;
                        }
                    } else {
                        src = A + (long)(bm + row) * ldA + gk;
                        sz = 16;
                    }
                }
                asm volatile("cp.async.cg.shared.global [%0], [%1], 16, %2;"
                             :: "r"(sbase + dsw), "l"(src), "r"(sz) : "memory");
            }
            {
                const float* src = B;
                int sz = 0;
                if ((bn + row) < N && gk < Kreal) {
                    src = B + (long)(bn + row) * ldB + gk;
                    sz = 16;
                }
                asm volatile("cp.async.cg.shared.global [%0], [%1], 16, %2;"
                             :: "r"(sbase + 16384u + dsw), "l"(src), "r"(sz) : "memory");
            }
        }
        asm volatile("cp.async.commit_group;" ::: "memory");
    };

    prefetch(0, 0);
    prefetch(1, 1);

    uint32_t aAddr[2];
    {
        int l16 = lane >> 4;
#pragma unroll
        for (int mi = 0; mi < 2; mi++) {
            int row = wm * 32 + mi * 16 + (lane & 15);
            aAddr[mi] = (uint32_t)(row * 128 + ((l16 ^ (row & 7)) << 4));
        }
    }
    uint32_t bAddr[4];
    {
        int brlo = (lane & 7) + ((lane >> 4) << 3);
        int bk = (lane >> 3) & 1;
#pragma unroll
        for (int nb = 0; nb < 4; nb++) {
            int row = wn * 64 + nb * 16 + brlo;
            bAddr[nb] = (uint32_t)(16384 + row * 128 + ((bk ^ (row & 7)) << 4));
        }
    }

    int st_cur = 0, st_pf = 2;
    for (int c = 0; c < nc; c++) {
        asm volatile("cp.async.wait_group 1;" ::: "memory");
        __syncthreads();
        if (c + 2 < nc) prefetch(c + 2, st_pf);
        else asm volatile("cp.async.commit_group;" ::: "memory");
        st_pf = (st_pf == 2) ? 0 : st_pf + 1;

        const uint32_t sbase = smb + (uint32_t)st_cur * 32768u;
        st_cur = (st_cur == 2) ? 0 : st_cur + 1;
#pragma unroll
        for (int ks = 0; ks < 4; ks++) {
            const uint32_t kx = (uint32_t)(ks << 5);
            uint32_t a0[4], a1[4];
            LDSM4(a0, sbase + (aAddr[0] ^ kx));
            LDSM4(a1, sbase + (aAddr[1] ^ kx));
#pragma unroll
            for (int nb = 0; nb < 4; nb++) {
                uint32_t bv[4];
                LDSM4(bv, sbase + (bAddr[nb] ^ kx));
                MMA_TF32(acc[0][nb * 2], a0, bv[0], bv[1]);
                MMA_TF32(acc[1][nb * 2], a1, bv[0], bv[1]);
                MMA_TF32(acc[0][nb * 2 + 1], a0, bv[2], bv[3]);
                MMA_TF32(acc[1][nb * 2 + 1], a1, bv[2], bv[3]);
            }
        }
    }

    // ---- epilogue ----
    const int qrow = lane >> 2, klo = lane & 3;
    float* sqsh = smf;
    if (EPI == 3) {
        __syncthreads();
        if (tid < 128) sqsh[tid] = 0.f;
        __syncthreads();
    }
    C += sCb * bz;
#pragma unroll
    for (int mi = 0; mi < 2; mi++) {
        int r0 = bm + wm * 32 + mi * 16 + qrow;
        float ra0 = 0.f, ra1 = 0.f;
        if (EPI == 2) {
            ra0 = rown[(long)rstride * bz + r0];
            ra1 = rown[(long)rstride * bz + r0 + 8];
        }
        float s_lo = 0.f, s_hi = 0.f;
#pragma unroll
        for (int ni = 0; ni < 8; ni++) {
            int colb = bn + wn * 64 + ni * 8;
            if (colb < N) {
                int col = colb + klo * 2;
                float2 v0, v1;
                if (EPI == 2) {
                    float cn0 = coln[(long)cstride * bz + col];
                    float cn1 = coln[(long)cstride * bz + col + 1];
                    v0.x = -TEMPC * (ra0 + cn0 - 2.f * acc[mi][ni][0]);
                    v0.y = -TEMPC * (ra0 + cn1 - 2.f * acc[mi][ni][1]);
                    v1.x = -TEMPC * (ra1 + cn0 - 2.f * acc[mi][ni][2]);
                    v1.y = -TEMPC * (ra1 + cn1 - 2.f * acc[mi][ni][3]);
                } else {
                    float bb0 = bias[col], bb1 = bias[col + 1];
                    v0.x = acc[mi][ni][0] + bb0; v0.y = acc[mi][ni][1] + bb1;
                    v1.x = acc[mi][ni][2] + bb0; v1.y = acc[mi][ni][3] + bb1;
                    if (EPI == 1) {
                        v0.x = fmaxf(v0.x, 0.f); v0.y = fmaxf(v0.y, 0.f);
                        v1.x = fmaxf(v1.x, 0.f); v1.y = fmaxf(v1.y, 0.f);
                    }
                    v0.x = rtf(v0.x); v0.y = rtf(v0.y);
                    v1.x = rtf(v1.x); v1.y = rtf(v1.y);
                    if (EPI == 3) {
                        s_lo += v0.x * v0.x + v0.y * v0.y;
                        s_hi += v1.x * v1.x + v1.y * v1.y;
                    }
                }
                *(float2*)(C + (long)r0 * ldC + col) = v0;
                *(float2*)(C + (long)(r0 + 8) * ldC + col) = v1;
            }
        }
        if (EPI == 3) {
            s_lo += __shfl_xor_sync(0xffffffffu, s_lo, 1);
            s_lo += __shfl_xor_sync(0xffffffffu, s_lo, 2);
            s_hi += __shfl_xor_sync(0xffffffffu, s_hi, 1);
            s_hi += __shfl_xor_sync(0xffffffffu, s_hi, 2);
            if (klo == 0) {
                int lr = wm * 32 + mi * 16 + qrow;
                atomicAdd(&sqsh[lr], s_lo);
                atomicAdd(&sqsh[lr + 8], s_hi);
            }
        }
    }
    if (EPI == 3) {
        __syncthreads();
        if (tid < 128) ((float*)coln)[bm + tid] = sqsh[tid];
    }
}

// ------------------------- fused prior + log_softmax + softmax (round-11 exact) -------------------------
__global__ __launch_bounds__(512) void softprior(
    const float* __restrict__ logits, const float* __restrict__ prior,
    float* __restrict__ out_logp, float* __restrict__ out_attn)
{
    __shared__ float sp[512][17];
    const int b = blockIdx.y, t0 = blockIdx.x * 16;
    const int tid = threadIdx.x, lane = tid & 31, wid = tid >> 5;
#pragma unroll
    for (int i = 0; i < 4; i++) {
        int f = tid + i * 512;
        int s = f >> 2;
        int tt4 = (f & 3) * 4;
        float4 v = *(const float4*)(prior + ((long)(b * 512 + s)) * 2048 + t0 + tt4);
        sp[s][tt4 + 0] = v.x; sp[s][tt4 + 1] = v.y;
        sp[s][tt4 + 2] = v.z; sp[s][tt4 + 3] = v.w;
    }
    __syncthreads();

    const long row = (long)b * 2048 + t0 + wid;
    const float* lrow = logits + row * 512;
    float v[16], e[16], p[16];
#pragma unroll
    for (int i = 0; i < 16; i++) v[i] = lrow[lane + 32 * i];
    float m = v[0];
#pragma unroll
    for (int i = 1; i < 16; i++) m = fmaxf(m, v[i]);
#pragma unroll
    for (int o = 16; o; o >>= 1) m = fmaxf(m, __shfl_xor_sync(0xffffffffu, m, o));
    float s1 = 0.f;
#pragma unroll
    for (int i = 0; i < 16; i++) { e[i] = __expf(v[i] - m); s1 += e[i]; }
#pragma unroll
    for (int o = 16; o; o >>= 1) s1 += __shfl_xor_sync(0xffffffffu, s1, o);
    float lse = m + __logf(s1);
    float den = 0.f;
#pragma unroll
    for (int i = 0; i < 16; i++) {
        p[i] = sp[lane + 32 * i][wid] + 1e-8f;
        den += e[i] * p[i];
    }
#pragma unroll
    for (int o = 16; o; o >>= 1) den += __shfl_xor_sync(0xffffffffu, den, o);
    float inv = 1.f / den;
    float* lpo = out_logp + row * 512;
    float* ao = out_attn + row * 512;
#pragma unroll
    for (int i = 0; i < 16; i++) {
        lpo[lane + 32 * i] = v[i] - lse + __logf(p[i]);
        ao[lane + 32 * i] = e[i] * p[i] * inv;
    }
}

// ------------------------- MAS forward DP v2 (round-11 exact) -------------------------
__global__ __launch_bounds__(256) void mas_fwd(const float* __restrict__ attn,
                                               unsigned* __restrict__ dirT)
{
    const int b = blockIdx.x;
    const int t = threadIdx.x;
    const int i0 = 2 * t;
    __shared__ float colb[16][512];
    __shared__ float nbr[2][256][2];
    const float* abase = attn + (long)b * 2048 * 512;
    const uint32_t cb = smem_u32(&colb[0][0]);

    nbr[0][t][0] = 0.f; nbr[0][t][1] = 0.f;
    for (int c = 0; c < 14; c += 2) {
#pragma unroll
        for (int cc = 0; cc < 2; cc++) {
            int col = c + cc;
            uint32_t dst = cb + (uint32_t)(((col & 15) * 512 + i0) * 4);
            asm volatile("cp.async.ca.shared.global [%0], [%1], 8;"
                         :: "r"(dst), "l"(abase + (long)col * 512 + i0) : "memory");
        }
        asm volatile("cp.async.commit_group;" ::: "memory");
    }
    float v0 = 0.f, v1 = 0.f;
    unsigned dw0 = 0, dw1 = 0;
    int p = 0;
    const int loA = (t == 0) ? 0 : (i0 - 1);

    for (int j0 = 0; j0 < 2048; j0 += 2) {
        asm volatile("cp.async.wait_group 6;" ::: "memory");
        __syncthreads();
        const int s0 = j0 & 15;
        float a0m1 = colb[s0][loA];
        float2 a0 = *(float2*)&colb[s0][i0];
        float2 a1 = *(float2*)&colb[s0 | 1][i0];
        float w0, w1;
        if (t == 0) { w0 = NEG_INF_DEV; w1 = NEG_INF_DEV; }
        else { w0 = nbr[p][t - 1][0]; w1 = nbr[p][t - 1][1]; }
        float w2 = v0, w3 = v1;
        {
            bool d3 = (w3 >= w2);
            bool d2 = (w2 >= w1);
            float c3 = fmaxf(w3, w2) + a0.y;
            float c2 = fmaxf(w2, w1) + a0.x;
            float c1 = fmaxf(w1, w0) + a0m1;
            w3 = (i0 + 1 <= j0) ? c3 : NEG_INF_DEV;
            w2 = (i0 <= j0) ? c2 : NEG_INF_DEV;
            w1 = (i0 - 1 <= j0) ? c1 : NEG_INF_DEV;
            dw1 |= ((unsigned)d3) << (j0 & 31);
            dw0 |= ((unsigned)d2) << (j0 & 31);
        }
        {
            const int j = j0 + 1;
            bool d3 = (w3 >= w2);
            bool d2 = (w2 >= w1);
            float c3 = fmaxf(w3, w2) + a1.y;
            float c2 = fmaxf(w2, w1) + a1.x;
            w3 = (i0 + 1 <= j) ? c3 : NEG_INF_DEV;
            w2 = (i0 <= j) ? c2 : NEG_INF_DEV;
            dw1 |= ((unsigned)d3) << (j & 31);
            dw0 |= ((unsigned)d2) << (j & 31);
        }
        v0 = w2; v1 = w3;
        nbr[p ^ 1][t][0] = v0; nbr[p ^ 1][t][1] = v1;
        p ^= 1;
        if (((j0 + 1) & 31) == 31) {
            int jw = j0 >> 5;
            dirT[((long)b * 512 + i0) * 64 + jw] = dw0;
            dirT[((long)b * 512 + i0 + 1) * 64 + jw] = dw1;
            dw0 = 0; dw1 = 0;
        }
        if (j0 + 14 < 2048) {
#pragma unroll
            for (int cc = 0; cc < 2; cc++) {
                int col = j0 + 14 + cc;
                uint32_t dst = cb + (uint32_t)(((col & 15) * 512 + i0) * 4);
                asm volatile("cp.async.ca.shared.global [%0], [%1], 8;"
                             :: "r"(dst), "l"(abase + (long)col * 512 + i0) : "memory");
            }
        }
        asm volatile("cp.async.commit_group;" ::: "memory");
    }
}

// ------------------------- MAS backtrack (round-11 exact) -------------------------
__global__ __launch_bounds__(512) void mas_bwd(const unsigned* __restrict__ dirT,
                                               int* __restrict__ idxg,
                                               float* __restrict__ durf)
{
    extern __shared__ unsigned sd[];
    __shared__ unsigned short sjlo[512];
    __shared__ unsigned short sidx[2048];
    int b = blockIdx.x, tid = threadIdx.x;
    for (int f = tid; f < 32768; f += 512) sd[f] = dirT[(long)b * 32768 + f];
    __syncthreads();
    if (tid == 0) {
        int idx = 511, j = 2047;
        while (idx > 0 && j >= 0) {
            unsigned w = sd[idx * 64 + (j >> 5)];
            int pj = j & 31;
            unsigned z = (~w) & ((2u << pj) - 1u);
            if (z == 0) {
                j -= pj + 1;
            } else {
                int hb = 31 - __clz(z);
                int jlo = (j & ~31) + hb;
                sjlo[idx] = (unsigned short)jlo;
                idx--;
                j = jlo - 1;
            }
        }
        sjlo[0] = 0;
    }
    __syncthreads();
    {
        int jlo = sjlo[tid];
        int jhi = (tid == 511) ? 2047 : ((int)sjlo[tid + 1] - 1);
        durf[b * 512 + tid] = (float)(jhi - jlo + 1);
        for (int j = jlo; j <= jhi; j++) sidx[j] = (unsigned short)tid;
    }
    __syncthreads();
    for (int f = tid; f < 2048; f += 512) idxg[b * 2048 + f] = (int)sidx[f];
}

__global__ __launch_bounds__(128) void mas_fill(const int* __restrict__ idxg,
                                                float* __restrict__ masout)
{
    long row = blockIdx.x;
    int id = idxg[row];
    int tid = threadIdx.x;
    float4 v = make_float4(0.f, 0.f, 0.f, 0.f);
    if ((id >> 2) == tid) ((float*)&v)[id & 3] = 1.f;
    ((float4*)(masout + row * 512))[tid] = v;
}

// ------------------------- launcher -------------------------
#define GSMEM 98304

extern "C" void kernel_launch(void* const* d_in, const int* in_sizes, int n_in,
                              void* d_out, int out_size) {
    const float* x   = (const float*)d_in[0];   // [32,512,512]
    const float* y   = (const float*)d_in[1];   // [32,2048,80]
    const float* pr  = (const float*)d_in[4];   // [32,512,2048]
    const float* kw1 = (const float*)d_in[5];
    const float* kb1 = (const float*)d_in[6];
    const float* kw2 = (const float*)d_in[7];
    const float* kb2 = (const float*)d_in[8];
    const float* qw1 = (const float*)d_in[9];
    const float* qb1 = (const float*)d_in[10];
    const float* qw2 = (const float*)d_in[11];
    const float* qb2 = (const float*)d_in[12];
    const float* qw3 = (const float*)d_in[13];
    const float* qb3 = (const float*)d_in[14];

    float* out = (float*)d_out;
    float* out_logp = out;
    float* out_attn = out + 33554432L;
    float* out_mas  = out + 67108864L;
    float* out_dur  = out + 100663296L;

    float *xr, *yr, *Wt1, *Wq1, *Wk2, *Wq2, *Wq3;
    float *h1, *kk, *k2, *hq1, *hq2, *qq, *q2, *logits;
    unsigned* dirT; int* idxg;
    cudaGetSymbolAddress((void**)&xr, g_xr);
    cudaGetSymbolAddress((void**)&yr, g_yr);
    cudaGetSymbolAddress((void**)&Wt1, g_Wt1);
    cudaGetSymbolAddress((void**)&Wq1, g_Wq1);
    cudaGetSymbolAddress((void**)&Wk2, g_Wk2);
    cudaGetSymbolAddress((void**)&Wq2, g_Wq2);
    cudaGetSymbolAddress((void**)&Wq3, g_Wq3);
    cudaGetSymbolAddress((void**)&h1, g_h1);
    cudaGetSymbolAddress((void**)&kk, g_kk);
    cudaGetSymbolAddress((void**)&k2, g_k2);
    cudaGetSymbolAddress((void**)&hq1, g_hq1);
    cudaGetSymbolAddress((void**)&hq2, g_hq2);
    cudaGetSymbolAddress((void**)&qq, g_qq);
    cudaGetSymbolAddress((void**)&q2, g_q2);
    cudaGetSymbolAddress((void**)&logits, g_logits);
    cudaGetSymbolAddress((void**)&dirT, g_dirT);
    cudaGetSymbolAddress((void**)&idxg, g_idx);

    cudaFuncSetAttribute(tgemm<1, 1, 512, 512>, cudaFuncAttributeMaxDynamicSharedMemorySize, GSMEM);
    cudaFuncSetAttribute(tgemm<1, 1, 80, 2048>, cudaFuncAttributeMaxDynamicSharedMemorySize, GSMEM);
    cudaFuncSetAttribute(tgemm<0, 1, 0, 0>, cudaFuncAttributeMaxDynamicSharedMemorySize, GSMEM);
    cudaFuncSetAttribute(tgemm<0, 2, 0, 0>, cudaFuncAttributeMaxDynamicSharedMemorySize, GSMEM);
    cudaFuncSetAttribute(tgemm<0, 3, 0, 0>, cudaFuncAttributeMaxDynamicSharedMemorySize, GSMEM);
    cudaFuncSetAttribute(mas_bwd, cudaFuncAttributeMaxDynamicSharedMemorySize, 131072);

    // 1: merged prep (tf32-round inputs + weights)
    prep_merged<<<RC_BLOCKS + PREP_BLOCKS, 256>>>(x, y, xr, yr,
                                                  kw1, qw1, kw2, qw2, qw3,
                                                  Wt1, Wq1, Wk2, Wq2, Wq3);

    // 2: k conv3 (im2col) M=16384 N=1024 K=1536, relu'd
    tgemm<1, 1, 512, 512><<<dim3(8, 128, 1), 256, GSMEM>>>(
        xr, Wt1, kb1, h1, 1024, 1536, 0, 1536, 1024,
        0, 0, 0, nullptr, nullptr, 0, 0);
    // 3: k 1x1 M=16384 N=128 K=1024 -> kk + k2 (rowsq fused)
    tgemm<0, 3, 0, 0><<<dim3(1, 128, 1), 256, GSMEM>>>(
        h1, Wk2, kb2, kk, 128, 1024, 1024, 1024, 128,
        0, 0, 0, nullptr, k2, 0, 0);

    // 4: q conv3 M=65536 N=160 K=240, relu'd
    tgemm<1, 1, 80, 2048><<<dim3(2, 512, 1), 256, GSMEM>>>(
        yr, Wq1, qb1, hq1, 160, 240, 0, 240, 160,
        0, 0, 0, nullptr, nullptr, 0, 0);
    // 5: q 1x1 N=80 K=160, relu'd
    tgemm<0, 1, 0, 0><<<dim3(1, 512, 1), 256, GSMEM>>>(
        hq1, Wq2, qb2, hq2, 80, 160, 160, 160, 80,
        0, 0, 0, nullptr, nullptr, 0, 0);
    // 6: q 1x1 N=128 K=80 -> qq + q2 (rowsq fused)
    tgemm<0, 3, 0, 0><<<dim3(1, 512, 1), 256, GSMEM>>>(
        hq2, Wq3, qb3, qq, 128, 80, 80, 80, 128,
        0, 0, 0, nullptr, q2, 0, 0);

    // 7: dist GEMM (batched): logits[b][t][s] = -TEMP*(q2+k2-2qk)
    tgemm<0, 2, 0, 0><<<dim3(4, 16, 32), 256, GSMEM>>>(
        qq, kk, nullptr, logits, 512, 128, 128, 128, 512,
        2048L * 128, 512L * 128, 2048L * 512, q2, k2, 2048, 512);

    // 8: fused prior + log_softmax + softmax
    softprior<<<dim3(128, 32), 512>>>(logits, pr, out_logp, out_attn);

    // 9-11: MAS forward DP + backtrack + fill
    mas_fwd<<<32, 256>>>(out_attn, dirT);
    mas_bwd<<<32, 512, 131072>>>(dirT, idxg, out_dur);
    mas_fill<<<65536, 128>>>(idxg, out_mas);
}

// round 17
// speedup vs baseline: 1.0770x; 1.0046x over previous
#include <cuda_runtime.h>
#include <math.h>
#include <stdint.h>

#define T_EN 512
#define T_DE 2048
#define TEMPC 0.0005f
#define NEG_INF_DEV __int_as_float(0xff800000)

__device__ __forceinline__ uint32_t f2tf(float x) {
    uint32_t r;
    asm("cvt.rna.tf32.f32 %0, %1;" : "=r"(r) : "f"(x));
    return r;
}
__device__ __forceinline__ float rtf(float x) { return __uint_as_float(f2tf(x)); }
__device__ __forceinline__ uint32_t smem_u32(const void* p) {
    uint32_t a;
    asm("{ .reg .u64 t; cvta.to.shared.u64 t, %1; cvt.u32.u64 %0, t; }" : "=r"(a) : "l"(p));
    return a;
}
#define LDSM4(r, addr) \
    asm volatile("ldmatrix.sync.aligned.m8n8.x4.shared.b16 {%0,%1,%2,%3}, [%4];" \
                 : "=r"((r)[0]), "=r"((r)[1]), "=r"((r)[2]), "=r"((r)[3]) : "r"(addr))
#define MMA_TF32(d, a, b0, b1) \
    asm volatile("mma.sync.aligned.m16n8k8.row.col.f32.tf32.tf32.f32 " \
                 "{%0,%1,%2,%3}, {%4,%5,%6,%7}, {%8,%9}, {%0,%1,%2,%3};" \
                 : "+f"((d)[0]), "+f"((d)[1]), "+f"((d)[2]), "+f"((d)[3]) \
                 : "r"((a)[0]), "r"((a)[1]), "r"((a)[2]), "r"((a)[3]), "r"(b0), "r"(b1))

// ------------------------- scratch (device globals) -------------------------
__device__ float g_xr[32L * 512 * 512];
__device__ float g_yr[32L * 2048 * 80];
__device__ float g_Wt1[1024L * 1536];
__device__ float g_Wq1[160 * 240];
__device__ float g_Wk2[128 * 1024];
__device__ float g_Wq2[80 * 160];
__device__ float g_Wq3[128 * 80];
__device__ float g_h1[16384L * 1024];
__device__ float g_kk[16384L * 128];
__device__ float g_k2[16384];
__device__ float g_hq1[65536L * 160];
__device__ float g_hq2[65536L * 80];
__device__ float g_qq[65536L * 128];
__device__ float g_q2[65536];
__device__ float g_logits[33554432L];
__device__ unsigned g_dirT[32L * 512 * 64];
__device__ int g_idx[32 * 2048];

// ------------------------- merged prep: roundcopy(x,y) + weight prep -------------------------
#define WT1_N (1024 * 512 * 3)
#define WQ1_N (160 * 80 * 3)
#define PREP_TOTAL (WT1_N + WQ1_N + 131072 + 12800 + 10240)
#define XN4 2097152
#define YN4 1310720
#define RC_BLOCKS ((XN4 + YN4 + 255) / 256)
#define PREP_BLOCKS ((PREP_TOTAL + 255) / 256)

__global__ void prep_merged(const float* __restrict__ x, const float* __restrict__ y,
                            float* __restrict__ xr, float* __restrict__ yr,
                            const float* __restrict__ kw1, const float* __restrict__ qw1,
                            const float* __restrict__ kw2, const float* __restrict__ qw2,
                            const float* __restrict__ qw3,
                            float* __restrict__ Wt1, float* __restrict__ Wq1,
                            float* __restrict__ Wk2, float* __restrict__ Wq2,
                            float* __restrict__ Wq3) {
    if (blockIdx.x < RC_BLOCKS) {
        int i = blockIdx.x * 256 + threadIdx.x;
        const float4* in;
        float4* out;
        if (i < XN4) { in = (const float4*)x + i; out = (float4*)xr + i; }
        else if (i < XN4 + YN4) { in = (const float4*)y + (i - XN4); out = (float4*)yr + (i - XN4); }
        else return;
        float4 v = *in;
        v.x = rtf(v.x); v.y = rtf(v.y); v.z = rtf(v.z); v.w = rtf(v.w);
        *out = v;
        return;
    }
    int i = (blockIdx.x - RC_BLOCKS) * 256 + threadIdx.x;
    if (i < WT1_N) {
        int n = i / 1536, rem = i - n * 1536;
        int ci = rem / 3, dt = rem - ci * 3;
        Wt1[(long)n * 1536 + dt * 512 + ci] = rtf(kw1[i]);
        return;
    }
    i -= WT1_N;
    if (i < WQ1_N) {
        int n = i / 240, rem = i - n * 240;
        int ci = rem / 3, dt = rem - ci * 3;
        Wq1[n * 240 + dt * 80 + ci] = rtf(qw1[i]);
        return;
    }
    i -= WQ1_N;
    if (i < 131072) { Wk2[i] = rtf(kw2[i]); return; }
    i -= 131072;
    if (i < 12800) { Wq2[i] = rtf(qw2[i]); return; }
    i -= 12800;
    if (i < 10240) { Wq3[i] = rtf(qw3[i]); return; }
}

// ------------------------- tf32 cp.async + ldmatrix GEMM (round-11 exact, FROZEN) -------------------------
template <int IM2COL, int EPI, int CIN, int TLEN>
__global__ __launch_bounds__(256, 2) void tgemm(
    const float* __restrict__ A, const float* __restrict__ B,
    const float* __restrict__ bias, float* __restrict__ C,
    int N, int Kreal, int ldA, int ldB, int ldC,
    long sAb, long sBb, long sCb,
    const float* __restrict__ rown, const float* __restrict__ coln,
    int rstride, int cstride)
{
    extern __shared__ float smf[];
    const uint32_t smb = smem_u32(smf);
    const int tid = threadIdx.x, lane = tid & 31, wid = tid >> 5;
    const int bn = blockIdx.x * 128, bm = blockIdx.y * 128, bz = blockIdx.z;
    A += sAb * bz; B += sBb * bz;
    const int wm = wid & 3, wn = wid >> 2;

    float acc[2][8][4];
#pragma unroll
    for (int i = 0; i < 2; i++)
#pragma unroll
        for (int j = 0; j < 8; j++)
#pragma unroll
            for (int q = 0; q < 4; q++) acc[i][j][q] = 0.f;

    const int nc = (Kreal + 31) >> 5;

    auto prefetch = [&](int c, int s) {
        const int kb = c << 5;
        const uint32_t sbase = smb + (uint32_t)s * 32768u;
#pragma unroll
        for (int r = 0; r < 4; r++) {
            int f = tid + r * 256;
            int row = f >> 3, kq = f & 7;
            int gk = kb + kq * 4;
            uint32_t dsw = (uint32_t)(row * 128 + ((kq ^ (row & 7)) << 4));
            {
                const float* src = A;
                int sz = 0;
                if (gk < Kreal) {
                    if (IM2COL) {
                        int gm = bm + row;
                        int bb = gm / TLEN;
                        int t = gm - bb * TLEN;
                        int dt = gk / CIN;
                        int ci = gk - dt * CIN;
                        int tt = t + dt - 1;
                        if (tt >= 0 && tt < TLEN) {
                            src = A + ((long)(bb * TLEN + tt)) * CIN + ci;
                            sz = 16;
                        }
                    } else {
                        src = A + (long)(bm + row) * ldA + gk;
                        sz = 16;
                    }
                }
                asm volatile("cp.async.cg.shared.global [%0], [%1], 16, %2;"
                             :: "r"(sbase + dsw), "l"(src), "r"(sz) : "memory");
            }
            {
                const float* src = B;
                int sz = 0;
                if ((bn + row) < N && gk < Kreal) {
                    src = B + (long)(bn + row) * ldB + gk;
                    sz = 16;
                }
                asm volatile("cp.async.cg.shared.global [%0], [%1], 16, %2;"
                             :: "r"(sbase + 16384u + dsw), "l"(src), "r"(sz) : "memory");
            }
        }
        asm volatile("cp.async.commit_group;" ::: "memory");
    };

    prefetch(0, 0);
    prefetch(1, 1);

    uint32_t aAddr[2];
    {
        int l16 = lane >> 4;
#pragma unroll
        for (int mi = 0; mi < 2; mi++) {
            int row = wm * 32 + mi * 16 + (lane & 15);
            aAddr[mi] = (uint32_t)(row * 128 + ((l16 ^ (row & 7)) << 4));
        }
    }
    uint32_t bAddr[4];
    {
        int brlo = (lane & 7) + ((lane >> 4) << 3);
        int bk = (lane >> 3) & 1;
#pragma unroll
        for (int nb = 0; nb < 4; nb++) {
            int row = wn * 64 + nb * 16 + brlo;
            bAddr[nb] = (uint32_t)(16384 + row * 128 + ((bk ^ (row & 7)) << 4));
        }
    }

    int st_cur = 0, st_pf = 2;
    for (int c = 0; c < nc; c++) {
        asm volatile("cp.async.wait_group 1;" ::: "memory");
        __syncthreads();
        if (c + 2 < nc) prefetch(c + 2, st_pf);
        else asm volatile("cp.async.commit_group;" ::: "memory");
        st_pf = (st_pf == 2) ? 0 : st_pf + 1;

        const uint32_t sbase = smb + (uint32_t)st_cur * 32768u;
        st_cur = (st_cur == 2) ? 0 : st_cur + 1;
#pragma unroll
        for (int ks = 0; ks < 4; ks++) {
            const uint32_t kx = (uint32_t)(ks << 5);
            uint32_t a0[4], a1[4];
            LDSM4(a0, sbase + (aAddr[0] ^ kx));
            LDSM4(a1, sbase + (aAddr[1] ^ kx));
#pragma unroll
            for (int nb = 0; nb < 4; nb++) {
                uint32_t bv[4];
                LDSM4(bv, sbase + (bAddr[nb] ^ kx));
                MMA_TF32(acc[0][nb * 2], a0, bv[0], bv[1]);
                MMA_TF32(acc[1][nb * 2], a1, bv[0], bv[1]);
                MMA_TF32(acc[0][nb * 2 + 1], a0, bv[2], bv[3]);
                MMA_TF32(acc[1][nb * 2 + 1], a1, bv[2], bv[3]);
            }
        }
    }

    // ---- epilogue ----
    const int qrow = lane >> 2, klo = lane & 3;
    float* sqsh = smf;
    if (EPI == 3) {
        __syncthreads();
        if (tid < 128) sqsh[tid] = 0.f;
        __syncthreads();
    }
    C += sCb * bz;
#pragma unroll
    for (int mi = 0; mi < 2; mi++) {
        int r0 = bm + wm * 32 + mi * 16 + qrow;
        float ra0 = 0.f, ra1 = 0.f;
        if (EPI == 2) {
            ra0 = rown[(long)rstride * bz + r0];
            ra1 = rown[(long)rstride * bz + r0 + 8];
        }
        float s_lo = 0.f, s_hi = 0.f;
#pragma unroll
        for (int ni = 0; ni < 8; ni++) {
            int colb = bn + wn * 64 + ni * 8;
            if (colb < N) {
                int col = colb + klo * 2;
                float2 v0, v1;
                if (EPI == 2) {
                    float cn0 = coln[(long)cstride * bz + col];
                    float cn1 = coln[(long)cstride * bz + col + 1];
                    v0.x = -TEMPC * (ra0 + cn0 - 2.f * acc[mi][ni][0]);
                    v0.y = -TEMPC * (ra0 + cn1 - 2.f * acc[mi][ni][1]);
                    v1.x = -TEMPC * (ra1 + cn0 - 2.f * acc[mi][ni][2]);
                    v1.y = -TEMPC * (ra1 + cn1 - 2.f * acc[mi][ni][3]);
                } else {
                    float bb0 = bias[col], bb1 = bias[col + 1];
                    v0.x = acc[mi][ni][0] + bb0; v0.y = acc[mi][ni][1] + bb1;
                    v1.x = acc[mi][ni][2] + bb0; v1.y = acc[mi][ni][3] + bb1;
                    if (EPI == 1) {
                        v0.x = fmaxf(v0.x, 0.f); v0.y = fmaxf(v0.y, 0.f);
                        v1.x = fmaxf(v1.x, 0.f); v1.y = fmaxf(v1.y, 0.f);
                    }
                    v0.x = rtf(v0.x); v0.y = rtf(v0.y);
                    v1.x = rtf(v1.x); v1.y = rtf(v1.y);
                    if (EPI == 3) {
                        s_lo += v0.x * v0.x + v0.y * v0.y;
                        s_hi += v1.x * v1.x + v1.y * v1.y;
                    }
                }
                *(float2*)(C + (long)r0 * ldC + col) = v0;
                *(float2*)(C + (long)(r0 + 8) * ldC + col) = v1;
            }
        }
        if (EPI == 3) {
            s_lo += __shfl_xor_sync(0xffffffffu, s_lo, 1);
            s_lo += __shfl_xor_sync(0xffffffffu, s_lo, 2);
            s_hi += __shfl_xor_sync(0xffffffffu, s_hi, 1);
            s_hi += __shfl_xor_sync(0xffffffffu, s_hi, 2);
            if (klo == 0) {
                int lr = wm * 32 + mi * 16 + qrow;
                atomicAdd(&sqsh[lr], s_lo);
                atomicAdd(&sqsh[lr + 8], s_hi);
            }
        }
    }
    if (EPI == 3) {
        __syncthreads();
        if (tid < 128) ((float*)coln)[bm + tid] = sqsh[tid];
    }
}

// ------------------------- fused prior + log_softmax + softmax -------------------------
// Blocks run in REVERSE order so the first logits reads hit the L2 tail left by the
// dist GEMM (logits ~128MB vs ~126MB L2). Pure index remap; arithmetic unchanged.
__global__ __launch_bounds__(512) void softprior(
    const float* __restrict__ logits, const float* __restrict__ prior,
    float* __restrict__ out_logp, float* __restrict__ out_attn)
{
    __shared__ float sp[512][17];
    const int b = 31 - blockIdx.y;
    const int t0 = (127 - blockIdx.x) * 16;
    const int tid = threadIdx.x, lane = tid & 31, wid = tid >> 5;
#pragma unroll
    for (int i = 0; i < 4; i++) {
        int f = tid + i * 512;
        int s = f >> 2;
        int tt4 = (f & 3) * 4;
        float4 v = *(const float4*)(prior + ((long)(b * 512 + s)) * 2048 + t0 + tt4);
        sp[s][tt4 + 0] = v.x; sp[s][tt4 + 1] = v.y;
        sp[s][tt4 + 2] = v.z; sp[s][tt4 + 3] = v.w;
    }
    __syncthreads();

    const long row = (long)b * 2048 + t0 + wid;
    const float* lrow = logits + row * 512;
    float v[16], e[16], p[16];
#pragma unroll
    for (int i = 0; i < 16; i++) v[i] = lrow[lane + 32 * i];
    float m = v[0];
#pragma unroll
    for (int i = 1; i < 16; i++) m = fmaxf(m, v[i]);
#pragma unroll
    for (int o = 16; o; o >>= 1) m = fmaxf(m, __shfl_xor_sync(0xffffffffu, m, o));
    float s1 = 0.f;
#pragma unroll
    for (int i = 0; i < 16; i++) { e[i] = __expf(v[i] - m); s1 += e[i]; }
#pragma unroll
    for (int o = 16; o; o >>= 1) s1 += __shfl_xor_sync(0xffffffffu, s1, o);
    float lse = m + __logf(s1);
    float den = 0.f;
#pragma unroll
    for (int i = 0; i < 16; i++) {
        p[i] = sp[lane + 32 * i][wid] + 1e-8f;
        den += e[i] * p[i];
    }
#pragma unroll
    for (int o = 16; o; o >>= 1) den += __shfl_xor_sync(0xffffffffu, den, o);
    float inv = 1.f / den;
    float* lpo = out_logp + row * 512;
    float* ao = out_attn + row * 512;
#pragma unroll
    for (int i = 0; i < 16; i++) {
        lpo[lane + 32 * i] = v[i] - lse + __logf(p[i]);
        ao[lane + 32 * i] = e[i] * p[i] * inv;
    }
}

// ------------------------- MAS forward DP v2 (round-11 exact, FROZEN) -------------------------
__global__ __launch_bounds__(256) void mas_fwd(const float* __restrict__ attn,
                                               unsigned* __restrict__ dirT)
{
    const int b = blockIdx.x;
    const int t = threadIdx.x;
    const int i0 = 2 * t;
    __shared__ float colb[16][512];
    __shared__ float nbr[2][256][2];
    const float* abase = attn + (long)b * 2048 * 512;
    const uint32_t cb = smem_u32(&colb[0][0]);

    nbr[0][t][0] = 0.f; nbr[0][t][1] = 0.f;
    for (int c = 0; c < 14; c += 2) {
#pragma unroll
        for (int cc = 0; cc < 2; cc++) {
            int col = c + cc;
            uint32_t dst = cb + (uint32_t)(((col & 15) * 512 + i0) * 4);
            asm volatile("cp.async.ca.shared.global [%0], [%1], 8;"
                         :: "r"(dst), "l"(abase + (long)col * 512 + i0) : "memory");
        }
        asm volatile("cp.async.commit_group;" ::: "memory");
    }
    float v0 = 0.f, v1 = 0.f;
    unsigned dw0 = 0, dw1 = 0;
    int p = 0;
    const int loA = (t == 0) ? 0 : (i0 - 1);

    for (int j0 = 0; j0 < 2048; j0 += 2) {
        asm volatile("cp.async.wait_group 6;" ::: "memory");
        __syncthreads();
        const int s0 = j0 & 15;
        float a0m1 = colb[s0][loA];
        float2 a0 = *(float2*)&colb[s0][i0];
        float2 a1 = *(float2*)&colb[s0 | 1][i0];
        float w0, w1;
        if (t == 0) { w0 = NEG_INF_DEV; w1 = NEG_INF_DEV; }
        else { w0 = nbr[p][t - 1][0]; w1 = nbr[p][t - 1][1]; }
        float w2 = v0, w3 = v1;
        {
            bool d3 = (w3 >= w2);
            bool d2 = (w2 >= w1);
            float c3 = fmaxf(w3, w2) + a0.y;
            float c2 = fmaxf(w2, w1) + a0.x;
            float c1 = fmaxf(w1, w0) + a0m1;
            w3 = (i0 + 1 <= j0) ? c3 : NEG_INF_DEV;
            w2 = (i0 <= j0) ? c2 : NEG_INF_DEV;
            w1 = (i0 - 1 <= j0) ? c1 : NEG_INF_DEV;
            dw1 |= ((unsigned)d3) << (j0 & 31);
            dw0 |= ((unsigned)d2) << (j0 & 31);
        }
        {
            const int j = j0 + 1;
            bool d3 = (w3 >= w2);
            bool d2 = (w2 >= w1);
            float c3 = fmaxf(w3, w2) + a1.y;
            float c2 = fmaxf(w2, w1) + a1.x;
            w3 = (i0 + 1 <= j) ? c3 : NEG_INF_DEV;
            w2 = (i0 <= j) ? c2 : NEG_INF_DEV;
            dw1 |= ((unsigned)d3) << (j & 31);
            dw0 |= ((unsigned)d2) << (j & 31);
        }
        v0 = w2; v1 = w3;
        nbr[p ^ 1][t][0] = v0; nbr[p ^ 1][t][1] = v1;
        p ^= 1;
        if (((j0 + 1) & 31) == 31) {
            int jw = j0 >> 5;
            dirT[((long)b * 512 + i0) * 64 + jw] = dw0;
            dirT[((long)b * 512 + i0 + 1) * 64 + jw] = dw1;
            dw0 = 0; dw1 = 0;
        }
        if (j0 + 14 < 2048) {
#pragma unroll
            for (int cc = 0; cc < 2; cc++) {
                int col = j0 + 14 + cc;
                uint32_t dst = cb + (uint32_t)(((col & 15) * 512 + i0) * 4);
                asm volatile("cp.async.ca.shared.global [%0], [%1], 8;"
                             :: "r"(dst), "l"(abase + (long)col * 512 + i0) : "memory");
            }
        }
        asm volatile("cp.async.commit_group;" ::: "memory");
    }
}

// ------------------------- MAS backtrack (round-11 exact) -------------------------
__global__ __launch_bounds__(512) void mas_bwd(const unsigned* __restrict__ dirT,
                                               int* __restrict__ idxg,
                                               float* __restrict__ durf)
{
    extern __shared__ unsigned sd[];
    __shared__ unsigned short sjlo[512];
    __shared__ unsigned short sidx[2048];
    int b = blockIdx.x, tid = threadIdx.x;
    for (int f = tid; f < 32768; f += 512) sd[f] = dirT[(long)b * 32768 + f];
    __syncthreads();
    if (tid == 0) {
        int idx = 511, j = 2047;
        while (idx > 0 && j >= 0) {
            unsigned w = sd[idx * 64 + (j >> 5)];
            int pj = j & 31;
            unsigned z = (~w) & ((2u << pj) - 1u);
            if (z == 0) {
                j -= pj + 1;
            } else {
                int hb = 31 - __clz(z);
                int jlo = (j & ~31) + hb;
                sjlo[idx] = (unsigned short)jlo;
                idx--;
                j = jlo - 1;
            }
        }
        sjlo[0] = 0;
    }
    __syncthreads();
    {
        int jlo = sjlo[tid];
        int jhi = (tid == 511) ? 2047 : ((int)sjlo[tid + 1] - 1);
        durf[b * 512 + tid] = (float)(jhi - jlo + 1);
        for (int j = jlo; j <= jhi; j++) sidx[j] = (unsigned short)tid;
    }
    __syncthreads();
    for (int f = tid; f < 2048; f += 512) idxg[b * 2048 + f] = (int)sidx[f];
}

__global__ __launch_bounds__(128) void mas_fill(const int* __restrict__ idxg,
                                                float* __restrict__ masout)
{
    long row = blockIdx.x;
    int id = idxg[row];
    int tid = threadIdx.x;
    float4 v = make_float4(0.f, 0.f, 0.f, 0.f);
    if ((id >> 2) == tid) ((float*)&v)[id & 3] = 1.f;
    ((float4*)(masout + row * 512))[tid] = v;
}

// ------------------------- launcher -------------------------
#define GSMEM 98304

extern "C" void kernel_launch(void* const* d_in, const int* in_sizes, int n_in,
                              void* d_out, int out_size) {
    const float* x   = (const float*)d_in[0];   // [32,512,512]
    const float* y   = (const float*)d_in[1];   // [32,2048,80]
    const float* pr  = (const float*)d_in[4];   // [32,512,2048]
    const float* kw1 = (const float*)d_in[5];
    const float* kb1 = (const float*)d_in[6];
    const float* kw2 = (const float*)d_in[7];
    const float* kb2 = (const float*)d_in[8];
    const float* qw1 = (const float*)d_in[9];
    const float* qb1 = (const float*)d_in[10];
    const float* qw2 = (const float*)d_in[11];
    const float* qb2 = (const float*)d_in[12];
    const float* qw3 = (const float*)d_in[13];
    const float* qb3 = (const float*)d_in[14];

    float* out = (float*)d_out;
    float* out_logp = out;
    float* out_attn = out + 33554432L;
    float* out_mas  = out + 67108864L;
    float* out_dur  = out + 100663296L;

    float *xr, *yr, *Wt1, *Wq1, *Wk2, *Wq2, *Wq3;
    float *h1, *kk, *k2, *hq1, *hq2, *qq, *q2, *logits;
    unsigned* dirT; int* idxg;
    cudaGetSymbolAddress((void**)&xr, g_xr);
    cudaGetSymbolAddress((void**)&yr, g_yr);
    cudaGetSymbolAddress((void**)&Wt1, g_Wt1);
    cudaGetSymbolAddress((void**)&Wq1, g_Wq1);
    cudaGetSymbolAddress((void**)&Wk2, g_Wk2);
    cudaGetSymbolAddress((void**)&Wq2, g_Wq2);
    cudaGetSymbolAddress((void**)&Wq3, g_Wq3);
    cudaGetSymbolAddress((void**)&h1, g_h1);
    cudaGetSymbolAddress((void**)&kk, g_kk);
    cudaGetSymbolAddress((void**)&k2, g_k2);
    cudaGetSymbolAddress((void**)&hq1, g_hq1);
    cudaGetSymbolAddress((void**)&hq2, g_hq2);
    cudaGetSymbolAddress((void**)&qq, g_qq);
    cudaGetSymbolAddress((void**)&q2, g_q2);
    cudaGetSymbolAddress((void**)&logits, g_logits);
    cudaGetSymbolAddress((void**)&dirT, g_dirT);
    cudaGetSymbolAddress((void**)&idxg, g_idx);

    cudaFuncSetAttribute(tgemm<1, 1, 512, 512>, cudaFuncAttributeMaxDynamicSharedMemorySize, GSMEM);
    cudaFuncSetAttribute(tgemm<1, 1, 80, 2048>, cudaFuncAttributeMaxDynamicSharedMemorySize, GSMEM);
    cudaFuncSetAttribute(tgemm<0, 1, 0, 0>, cudaFuncAttributeMaxDynamicSharedMemorySize, GSMEM);
    cudaFuncSetAttribute(tgemm<0, 2, 0, 0>, cudaFuncAttributeMaxDynamicSharedMemorySize, GSMEM);
    cudaFuncSetAttribute(tgemm<0, 3, 0, 0>, cudaFuncAttributeMaxDynamicSharedMemorySize, GSMEM);
    cudaFuncSetAttribute(mas_bwd, cudaFuncAttributeMaxDynamicSharedMemorySize, 131072);

    // 1: merged prep (tf32-round inputs + weights)
    prep_merged<<<RC_BLOCKS + PREP_BLOCKS, 256>>>(x, y, xr, yr,
                                                  kw1, qw1, kw2, qw2, qw3,
                                                  Wt1, Wq1, Wk2, Wq2, Wq3);

    // 2: k conv3 (im2col) M=16384 N=1024 K=1536, relu'd
    tgemm<1, 1, 512, 512><<<dim3(8, 128, 1), 256, GSMEM>>>(
        xr, Wt1, kb1, h1, 1024, 1536, 0, 1536, 1024,
        0, 0, 0, nullptr, nullptr, 0, 0);
    // 3: k 1x1 M=16384 N=128 K=1024 -> kk + k2 (rowsq fused)
    tgemm<0, 3, 0, 0><<<dim3(1, 128, 1), 256, GSMEM>>>(
        h1, Wk2, kb2, kk, 128, 1024, 1024, 1024, 128,
        0, 0, 0, nullptr, k2, 0, 0);

    // 4: q conv3 M=65536 N=160 K=240, relu'd
    tgemm<1, 1, 80, 2048><<<dim3(2, 512, 1), 256, GSMEM>>>(
        yr, Wq1, qb1, hq1, 160, 240, 0, 240, 160,
        0, 0, 0, nullptr, nullptr, 0, 0);
    // 5: q 1x1 N=80 K=160, relu'd
    tgemm<0, 1, 0, 0><<<dim3(1, 512, 1), 256, GSMEM>>>(
        hq1, Wq2, qb2, hq2, 80, 160, 160, 160, 80,
        0, 0, 0, nullptr, nullptr, 0, 0);
    // 6: q 1x1 N=128 K=80 -> qq + q2 (rowsq fused)
    tgemm<0, 3, 0, 0><<<dim3(1, 512, 1), 256, GSMEM>>>(
        hq2, Wq3, qb3, qq, 128, 80, 80, 80, 128,
        0, 0, 0, nullptr, q2, 0, 0);

    // 7: dist GEMM (batched): logits[b][t][s] = -TEMP*(q2+k2-2qk)
    tgemm<0, 2, 0, 0><<<dim3(4, 16, 32), 256, GSMEM>>>(
        qq, kk, nullptr, logits, 512, 128, 128, 128, 512,
        2048L * 128, 512L * 128, 2048L * 512, q2, k2, 2048, 512);

    // 8: fused prior + log_softmax + softmax (reverse block order for L2 reuse)
    softprior<<<dim3(128, 32), 512>>>(logits, pr, out_logp, out_attn);

    // 9-11: MAS forward DP + backtrack + fill
    mas_fwd<<<32, 256>>>(out_attn, dirT);
    mas_bwd<<<32, 512, 131072>>>(dirT, idxg, out_dur);
    mas_fill<<<65536, 128>>>(idxg, out_mas);
}